// round 3
// baseline (speedup 1.0000x reference)
#include <cuda_runtime.h>
#include <math.h>

#define MAXN 100000
#define MAXE 3200000

// Scratch (device globals — allocation-free per harness rules)
__device__ float g_deg[MAXN];
__device__ float g_dis[MAXN];
__device__ float g_h1[(size_t)MAXN * 64];
__device__ float g_agg1[(size_t)MAXN * 64];
__device__ float g_h2[(size_t)MAXN * 32];
__device__ float g_agg2[(size_t)MAXN * 32];

__device__ __forceinline__ float elu_f(float v) { return v > 0.f ? v : expm1f(v); }

// ---------------- degree / normalization ----------------
__global__ void k_zero_deg(int N) {
    int i = blockIdx.x * blockDim.x + threadIdx.x;
    if (i < N) g_deg[i] = 0.f;
}

__global__ void k_count(const int* __restrict__ col, int E) {
    int e = blockIdx.x * blockDim.x + threadIdx.x;
    if (e < E) atomicAdd(&g_deg[col[e]], 1.0f);
}

__global__ void k_dis(int N) {
    int i = blockIdx.x * blockDim.x + threadIdx.x;
    if (i < N) g_dis[i] = rsqrtf(g_deg[i] + 1.0f);   // +1 = self loop
}

// ---------------- GEMM 1: h1 = x @ W1  (256 -> 64) ----------------
// One thread per row; full W1 (256x64 = 64KB) in dynamic smem, broadcast reads.
__global__ void k_gemm1(const float* __restrict__ x, const float* __restrict__ W1, int N) {
    extern __shared__ float Ws[];  // 256*64 floats
    {
        float4* d = (float4*)Ws;
        const float4* s = (const float4*)W1;
        for (int i = threadIdx.x; i < 256 * 64 / 4; i += blockDim.x) d[i] = s[i];
    }
    __syncthreads();
    int row = blockIdx.x * blockDim.x + threadIdx.x;
    if (row >= N) return;

    float acc[64];
#pragma unroll
    for (int j = 0; j < 64; j++) acc[j] = 0.f;

    const float4* X4 = (const float4*)(x + (size_t)row * 256);
#pragma unroll 4
    for (int k4 = 0; k4 < 64; k4++) {
        float4 xv = X4[k4];
        float xs[4] = {xv.x, xv.y, xv.z, xv.w};
#pragma unroll
        for (int kk = 0; kk < 4; kk++) {
            float xk = xs[kk];
            const float4* Wr = (const float4*)(Ws + (k4 * 4 + kk) * 64);
#pragma unroll
            for (int j4 = 0; j4 < 16; j4++) {
                float4 w = Wr[j4];
                acc[4 * j4 + 0] += xk * w.x;
                acc[4 * j4 + 1] += xk * w.y;
                acc[4 * j4 + 2] += xk * w.z;
                acc[4 * j4 + 3] += xk * w.w;
            }
        }
    }
    float4* out = (float4*)(g_h1 + (size_t)row * 64);
#pragma unroll
    for (int j4 = 0; j4 < 16; j4++)
        out[j4] = make_float4(acc[4 * j4], acc[4 * j4 + 1], acc[4 * j4 + 2], acc[4 * j4 + 3]);
}

// ---------------- self-loop init (also zero-init): agg = h * dis^2 ----------------
__global__ void k_selfinit1(int N) {
    int t = blockIdx.x * blockDim.x + threadIdx.x;
    int i = t >> 4, l = t & 15;
    if (i >= N) return;
    float d = g_dis[i];
    float s = d * d;
    float4 v = ((const float4*)g_h1)[(size_t)i * 16 + l];
    ((float4*)g_agg1)[(size_t)i * 16 + l] = make_float4(v.x * s, v.y * s, v.z * s, v.w * s);
}

__global__ void k_selfinit2(int N) {
    int t = blockIdx.x * blockDim.x + threadIdx.x;
    int i = t >> 3, l = t & 7;
    if (i >= N) return;
    float d = g_dis[i];
    float s = d * d;
    float4 v = ((const float4*)g_h2)[(size_t)i * 8 + l];
    ((float4*)g_agg2)[(size_t)i * 8 + l] = make_float4(v.x * s, v.y * s, v.z * s, v.w * s);
}

// ---------------- edge scatter: agg[col] += h[row] * dis[row]*dis[col] ----------------
// 16 threads/edge (64ch) via red.global.add.v4.f32 (vector reduction, sm_90+)
__global__ void k_scatter1(const int* __restrict__ rowi, const int* __restrict__ coli, int E) {
    long long t = (long long)blockIdx.x * blockDim.x + threadIdx.x;
    int e = (int)(t >> 4);
    int l = (int)(t & 15);
    if (e >= E) return;
    int r = __ldg(rowi + e);
    int c = __ldg(coli + e);
    float nm = g_dis[r] * g_dis[c];
    float4 v = ((const float4*)g_h1)[(size_t)r * 16 + l];
    float* dst = g_agg1 + ((size_t)c * 16 + l) * 4;
    asm volatile("red.global.add.v4.f32 [%0], {%1,%2,%3,%4};" ::
                 "l"(dst), "f"(v.x * nm), "f"(v.y * nm), "f"(v.z * nm), "f"(v.w * nm)
                 : "memory");
}

// 8 threads/edge (32ch)
__global__ void k_scatter2(const int* __restrict__ rowi, const int* __restrict__ coli, int E) {
    long long t = (long long)blockIdx.x * blockDim.x + threadIdx.x;
    int e = (int)(t >> 3);
    int l = (int)(t & 7);
    if (e >= E) return;
    int r = __ldg(rowi + e);
    int c = __ldg(coli + e);
    float nm = g_dis[r] * g_dis[c];
    float4 v = ((const float4*)g_h2)[(size_t)r * 8 + l];
    float* dst = g_agg2 + ((size_t)c * 8 + l) * 4;
    asm volatile("red.global.add.v4.f32 [%0], {%1,%2,%3,%4};" ::
                 "l"(dst), "f"(v.x * nm), "f"(v.y * nm), "f"(v.z * nm), "f"(v.w * nm)
                 : "memory");
}

// ---------------- GEMM 2: h2 = elu(agg1 + b1) @ W2  (64 -> 32), ELU fused on load ----------------
__global__ void k_gemm2(const float* __restrict__ W2, const float* __restrict__ b1, int N) {
    __shared__ float Ws[64 * 32];
    __shared__ float bs[64];
    for (int i = threadIdx.x; i < 64 * 32; i += blockDim.x) Ws[i] = W2[i];
    if (threadIdx.x < 64) bs[threadIdx.x] = b1[threadIdx.x];
    __syncthreads();
    int row = blockIdx.x * blockDim.x + threadIdx.x;
    if (row >= N) return;

    float acc[32];
#pragma unroll
    for (int j = 0; j < 32; j++) acc[j] = 0.f;

    const float4* A4 = (const float4*)(g_agg1 + (size_t)row * 64);
#pragma unroll 4
    for (int k4 = 0; k4 < 16; k4++) {
        float4 v = A4[k4];
        float xs[4] = {v.x, v.y, v.z, v.w};
#pragma unroll
        for (int kk = 0; kk < 4; kk++) {
            int k = k4 * 4 + kk;
            float xk = elu_f(xs[kk] + bs[k]);
            const float4* Wr = (const float4*)(Ws + k * 32);
#pragma unroll
            for (int j4 = 0; j4 < 8; j4++) {
                float4 w = Wr[j4];
                acc[4 * j4 + 0] += xk * w.x;
                acc[4 * j4 + 1] += xk * w.y;
                acc[4 * j4 + 2] += xk * w.z;
                acc[4 * j4 + 3] += xk * w.w;
            }
        }
    }
    float4* out = (float4*)(g_h2 + (size_t)row * 32);
#pragma unroll
    for (int j4 = 0; j4 < 8; j4++)
        out[j4] = make_float4(acc[4 * j4], acc[4 * j4 + 1], acc[4 * j4 + 2], acc[4 * j4 + 3]);
}

// ---------------- final head: out = elu(agg2 + b2) . Wc + bc ----------------
__global__ void k_final(const float* __restrict__ Wc, const float* __restrict__ b2,
                        const float* __restrict__ bc, float* __restrict__ out, int N) {
    __shared__ float wcs[32], b2s[32];
    if (threadIdx.x < 32) {
        wcs[threadIdx.x] = Wc[threadIdx.x];
        b2s[threadIdx.x] = b2[threadIdx.x];
    }
    __syncthreads();
    int i = blockIdx.x * blockDim.x + threadIdx.x;
    if (i >= N) return;
    const float4* A4 = (const float4*)(g_agg2 + (size_t)i * 32);
    float s = 0.f;
#pragma unroll
    for (int j4 = 0; j4 < 8; j4++) {
        float4 v = A4[j4];
        s += elu_f(v.x + b2s[4 * j4 + 0]) * wcs[4 * j4 + 0];
        s += elu_f(v.y + b2s[4 * j4 + 1]) * wcs[4 * j4 + 1];
        s += elu_f(v.z + b2s[4 * j4 + 2]) * wcs[4 * j4 + 2];
        s += elu_f(v.w + b2s[4 * j4 + 3]) * wcs[4 * j4 + 3];
    }
    out[i] = s + __ldg(bc);
}

extern "C" void kernel_launch(void* const* d_in, const int* in_sizes, int n_in,
                              void* d_out, int out_size) {
    const float* x = (const float*)d_in[0];
    const int* ei = (const int*)d_in[1];   // JAX default x64-disabled -> int32
    const float* W1 = (const float*)d_in[2];
    const float* b1 = (const float*)d_in[3];
    const float* W2 = (const float*)d_in[4];
    const float* b2 = (const float*)d_in[5];
    const float* Wc = (const float*)d_in[6];
    const float* bc = (const float*)d_in[7];
    float* out = (float*)d_out;

    int N = in_sizes[0] / 256;
    int E = in_sizes[1] / 2;
    const int* erow = ei;       // edge_index[0] = source (gather)
    const int* ecol = ei + E;   // edge_index[1] = target (aggregation)

    cudaFuncSetAttribute(k_gemm1, cudaFuncAttributeMaxDynamicSharedMemorySize, 65536);

    const int T = 256;
    // normalization
    k_zero_deg<<<(N + T - 1) / T, T>>>(N);
    k_count<<<(E + T - 1) / T, T>>>(ecol, E);
    k_dis<<<(N + T - 1) / T, T>>>(N);
    // layer 1
    k_gemm1<<<(N + T - 1) / T, T, 65536>>>(x, W1, N);
    {
        long long th = (long long)N * 16;
        k_selfinit1<<<(int)((th + T - 1) / T), T>>>(N);
    }
    {
        long long th = (long long)E * 16;
        k_scatter1<<<(int)((th + T - 1) / T), T>>>(erow, ecol, E);
    }
    // layer 2 (ELU+b1 fused into gemm2 load)
    k_gemm2<<<(N + T - 1) / T, T>>>(W2, b1, N);
    {
        long long th = (long long)N * 8;
        k_selfinit2<<<(int)((th + T - 1) / T), T>>>(N);
    }
    {
        long long th = (long long)E * 8;
        k_scatter2<<<(int)((th + T - 1) / T), T>>>(erow, ecol, E);
    }
    // head (ELU+b2 fused)
    k_final<<<(N + T - 1) / T, T>>>(Wc, b2, bc, out, N);
}

// round 6
// speedup vs baseline: 1.0497x; 1.0497x over previous
#include <cuda_runtime.h>
#include <math.h>

#define MAXN 100000
#define MAXE 3200000

// Scratch (device globals — allocation-free per harness rules)
__device__ float g_deg[MAXN];
__device__ float g_dis[MAXN];
__device__ float g_h1s[(size_t)MAXN * 64];   // h1 * dis[row]
__device__ float g_agg1[(size_t)MAXN * 64];  // sum of h1s over in-edges (+ self), unscaled by dis[col]
__device__ float g_h2s[(size_t)MAXN * 32];   // h2 * dis[row]
__device__ float g_agg2[(size_t)MAXN * 32];

__device__ __forceinline__ float elu_f(float v) { return v > 0.f ? v : expm1f(v); }

// ---------------- degree / normalization ----------------
__global__ void k_zero_deg(int N) {
    int i = blockIdx.x * blockDim.x + threadIdx.x;
    if (i < N) g_deg[i] = 0.f;
}

__global__ void k_count(const int* __restrict__ col, int E) {
    int e = blockIdx.x * blockDim.x + threadIdx.x;
    if (e < E) atomicAdd(&g_deg[col[e]], 1.0f);
}

__global__ void k_dis(int N) {
    int i = blockIdx.x * blockDim.x + threadIdx.x;
    if (i < N) g_dis[i] = rsqrtf(g_deg[i] + 1.0f);   // +1 = self loop
}

// ---------------- GEMM 1: h1s = (x @ W1) * dis[row]  (256 -> 64) ----------------
// Register-tiled: 256 rows x 64 cols per block, 256 threads, 8x8 micro-tile.
// x staged transposed in smem -> 64 FMA per 4 LDS.128.
// Epilogue writes h1s AND agg1 (self-loop init), killing the selfinit pass.
__global__ void __launch_bounds__(256) k_gemm1(const float* __restrict__ x,
                                               const float* __restrict__ W1, int N) {
    __shared__ float xT[32][260];   // [k][m], pad keeps 16B alignment (260*4=1040=65*16)
    __shared__ float Wt[32][64];    // [k][n]

    const int tid = threadIdx.x;
    const int m0 = blockIdx.x * 256;
    const int r0 = (tid >> 3) * 8;   // row offset within block (0..248)
    const int c0 = (tid & 7) * 8;    // col offset (0..56)

    float acc[8][8];
#pragma unroll
    for (int i = 0; i < 8; i++)
#pragma unroll
        for (int j = 0; j < 8; j++) acc[i][j] = 0.f;

    const int myrow = m0 + tid;   // row this thread stages
    for (int kt = 0; kt < 8; kt++) {
        const int k0 = kt * 32;
        // stage x[m0..m0+255][k0..k0+31] transposed
        {
            float4 v[8];
            if (myrow < N) {
                const float4* src = (const float4*)(x + (size_t)myrow * 256 + k0);
#pragma unroll
                for (int q = 0; q < 8; q++) v[q] = src[q];
            } else {
#pragma unroll
                for (int q = 0; q < 8; q++) v[q] = make_float4(0.f, 0.f, 0.f, 0.f);
            }
#pragma unroll
            for (int q = 0; q < 8; q++) {
                xT[4 * q + 0][tid] = v[q].x;
                xT[4 * q + 1][tid] = v[q].y;
                xT[4 * q + 2][tid] = v[q].z;
                xT[4 * q + 3][tid] = v[q].w;
            }
        }
        // stage W1[k0..k0+31][0..63] (already [k][n] layout)
        {
            const float4* src = (const float4*)(W1 + (size_t)k0 * 64);
            float4* dst = (float4*)Wt;
            dst[tid] = src[tid];
            dst[tid + 256] = src[tid + 256];
        }
        __syncthreads();

#pragma unroll
        for (int kk = 0; kk < 32; kk++) {
            float4 xa = *(const float4*)&xT[kk][r0];
            float4 xb = *(const float4*)&xT[kk][r0 + 4];
            float4 wa = *(const float4*)&Wt[kk][c0];
            float4 wb = *(const float4*)&Wt[kk][c0 + 4];
            float xs[8] = {xa.x, xa.y, xa.z, xa.w, xb.x, xb.y, xb.z, xb.w};
            float ws[8] = {wa.x, wa.y, wa.z, wa.w, wb.x, wb.y, wb.z, wb.w};
#pragma unroll
            for (int i = 0; i < 8; i++)
#pragma unroll
                for (int j = 0; j < 8; j++) acc[i][j] += xs[i] * ws[j];
        }
        __syncthreads();
    }

    // epilogue: scale by dis[m], write h1s and agg1 (= self-loop init)
#pragma unroll
    for (int i = 0; i < 8; i++) {
        int m = m0 + r0 + i;
        if (m >= N) break;
        float d = g_dis[m];
        float4 a = make_float4(acc[i][0] * d, acc[i][1] * d, acc[i][2] * d, acc[i][3] * d);
        float4 b = make_float4(acc[i][4] * d, acc[i][5] * d, acc[i][6] * d, acc[i][7] * d);
        float4* o1 = (float4*)(g_h1s + (size_t)m * 64 + c0);
        float4* o2 = (float4*)(g_agg1 + (size_t)m * 64 + c0);
        o1[0] = a; o1[1] = b;
        o2[0] = a; o2[1] = b;
    }
}

// ---------------- edge scatter: agg[c] += h_s[r]  (norm folded out) ----------------
__global__ void k_scatter1(const int* __restrict__ rowi, const int* __restrict__ coli, int E) {
    long long t = (long long)blockIdx.x * blockDim.x + threadIdx.x;
    int e = (int)(t >> 4);
    int l = (int)(t & 15);
    if (e >= E) return;
    int r = __ldg(rowi + e);
    int c = __ldg(coli + e);
    float4 v = ((const float4*)g_h1s)[(size_t)r * 16 + l];
    float* dst = g_agg1 + (size_t)c * 64 + l * 4;
    asm volatile("red.global.add.v4.f32 [%0], {%1,%2,%3,%4};" ::
                 "l"(dst), "f"(v.x), "f"(v.y), "f"(v.z), "f"(v.w)
                 : "memory");
}

__global__ void k_scatter2(const int* __restrict__ rowi, const int* __restrict__ coli, int E) {
    long long t = (long long)blockIdx.x * blockDim.x + threadIdx.x;
    int e = (int)(t >> 3);
    int l = (int)(t & 7);
    if (e >= E) return;
    int r = __ldg(rowi + e);
    int c = __ldg(coli + e);
    float4 v = ((const float4*)g_h2s)[(size_t)r * 8 + l];
    float* dst = g_agg2 + (size_t)c * 32 + l * 4;
    asm volatile("red.global.add.v4.f32 [%0], {%1,%2,%3,%4};" ::
                 "l"(dst), "f"(v.x), "f"(v.y), "f"(v.z), "f"(v.w)
                 : "memory");
}

// ---------------- GEMM 2: h2s = (elu(dis*agg1 + b1) @ W2) * dis  (64 -> 32) ----------------
// 256 rows x 32 cols per block, 128 threads, 8x8 micro-tile.
// ELU + bias + dis[col] applied during smem staging. Epilogue writes h2s AND agg2.
__global__ void __launch_bounds__(128) k_gemm2(const float* __restrict__ W2,
                                               const float* __restrict__ b1, int N) {
    __shared__ float aT[32][260];   // [k][m]
    __shared__ float Wt[64][32];    // full W2
    __shared__ float bs[64];

    const int tid = threadIdx.x;
    const int m0 = blockIdx.x * 256;
    const int r0 = (tid >> 2) * 8;   // 0..248
    const int c0 = (tid & 3) * 8;    // 0..24

    // one-time loads
    {
        const float4* src = (const float4*)W2;
        float4* dst = (float4*)Wt;
#pragma unroll
        for (int q = 0; q < 4; q++) dst[tid + 128 * q] = src[tid + 128 * q];
        if (tid < 64) bs[tid] = b1[tid];
    }
    __syncthreads();

    float acc[8][8];
#pragma unroll
    for (int i = 0; i < 8; i++)
#pragma unroll
        for (int j = 0; j < 8; j++) acc[i][j] = 0.f;

    for (int kt = 0; kt < 2; kt++) {
        const int k0 = kt * 32;
        // stage elu(dis[m]*agg1[m][k] + b1[k]) transposed; 2 rows per thread
        __syncthreads();
#pragma unroll
        for (int half = 0; half < 2; half++) {
            int lm = tid + 128 * half;
            int m = m0 + lm;
            if (m < N) {
                float d = g_dis[m];
                const float4* src = (const float4*)(g_agg1 + (size_t)m * 64 + k0);
#pragma unroll
                for (int q = 0; q < 8; q++) {
                    float4 v = src[q];
                    aT[4 * q + 0][lm] = elu_f(d * v.x + bs[k0 + 4 * q + 0]);
                    aT[4 * q + 1][lm] = elu_f(d * v.y + bs[k0 + 4 * q + 1]);
                    aT[4 * q + 2][lm] = elu_f(d * v.z + bs[k0 + 4 * q + 2]);
                    aT[4 * q + 3][lm] = elu_f(d * v.w + bs[k0 + 4 * q + 3]);
                }
            } else {
#pragma unroll
                for (int q = 0; q < 32; q++) aT[q][lm] = 0.f;
            }
        }
        __syncthreads();

#pragma unroll
        for (int kk = 0; kk < 32; kk++) {
            float4 xa = *(const float4*)&aT[kk][r0];
            float4 xb = *(const float4*)&aT[kk][r0 + 4];
            float4 wa = *(const float4*)&Wt[k0 + kk][c0];
            float4 wb = *(const float4*)&Wt[k0 + kk][c0 + 4];
            float xs[8] = {xa.x, xa.y, xa.z, xa.w, xb.x, xb.y, xb.z, xb.w};
            float ws[8] = {wa.x, wa.y, wa.z, wa.w, wb.x, wb.y, wb.z, wb.w};
#pragma unroll
            for (int i = 0; i < 8; i++)
#pragma unroll
                for (int j = 0; j < 8; j++) acc[i][j] += xs[i] * ws[j];
        }
    }

#pragma unroll
    for (int i = 0; i < 8; i++) {
        int m = m0 + r0 + i;
        if (m >= N) break;
        float d = g_dis[m];
        float4 a = make_float4(acc[i][0] * d, acc[i][1] * d, acc[i][2] * d, acc[i][3] * d);
        float4 b = make_float4(acc[i][4] * d, acc[i][5] * d, acc[i][6] * d, acc[i][7] * d);
        float4* o1 = (float4*)(g_h2s + (size_t)m * 32 + c0);
        float4* o2 = (float4*)(g_agg2 + (size_t)m * 32 + c0);
        o1[0] = a; o1[1] = b;
        o2[0] = a; o2[1] = b;
    }
}

// ---------------- final head: out = elu(dis*agg2 + b2) . Wc + bc ----------------
__global__ void k_final(const float* __restrict__ Wc, const float* __restrict__ b2,
                        const float* __restrict__ bc, float* __restrict__ out, int N) {
    __shared__ float wcs[32], b2s[32];
    if (threadIdx.x < 32) {
        wcs[threadIdx.x] = Wc[threadIdx.x];
        b2s[threadIdx.x] = b2[threadIdx.x];
    }
    __syncthreads();
    int i = blockIdx.x * blockDim.x + threadIdx.x;
    if (i >= N) return;
    float d = g_dis[i];
    const float4* A4 = (const float4*)(g_agg2 + (size_t)i * 32);
    float s = 0.f;
#pragma unroll
    for (int j4 = 0; j4 < 8; j4++) {
        float4 v = A4[j4];
        s += elu_f(d * v.x + b2s[4 * j4 + 0]) * wcs[4 * j4 + 0];
        s += elu_f(d * v.y + b2s[4 * j4 + 1]) * wcs[4 * j4 + 1];
        s += elu_f(d * v.z + b2s[4 * j4 + 2]) * wcs[4 * j4 + 2];
        s += elu_f(d * v.w + b2s[4 * j4 + 3]) * wcs[4 * j4 + 3];
    }
    out[i] = s + __ldg(bc);
}

extern "C" void kernel_launch(void* const* d_in, const int* in_sizes, int n_in,
                              void* d_out, int out_size) {
    const float* x = (const float*)d_in[0];
    const int* ei = (const int*)d_in[1];   // int32 (JAX x64 disabled)
    const float* W1 = (const float*)d_in[2];
    const float* b1 = (const float*)d_in[3];
    const float* W2 = (const float*)d_in[4];
    const float* b2 = (const float*)d_in[5];
    const float* Wc = (const float*)d_in[6];
    const float* bc = (const float*)d_in[7];
    float* out = (float*)d_out;

    int N = in_sizes[0] / 256;
    int E = in_sizes[1] / 2;
    const int* erow = ei;       // source (gather)
    const int* ecol = ei + E;   // target (aggregation)

    const int T = 256;
    // normalization
    k_zero_deg<<<(N + T - 1) / T, T>>>(N);
    k_count<<<(E + T - 1) / T, T>>>(ecol, E);
    k_dis<<<(N + T - 1) / T, T>>>(N);
    // layer 1
    k_gemm1<<<(N + 255) / 256, 256>>>(x, W1, N);
    {
        long long th = (long long)E * 16;
        k_scatter1<<<(int)((th + T - 1) / T), T>>>(erow, ecol, E);
    }
    // layer 2
    k_gemm2<<<(N + 255) / 256, 128>>>(W2, b1, N);
    {
        long long th = (long long)E * 8;
        k_scatter2<<<(int)((th + T - 1) / T), T>>>(erow, ecol, E);
    }
    // head
    k_final<<<(N + T - 1) / T, T>>>(Wc, b2, bc, out, N);
}